// round 2
// baseline (speedup 1.0000x reference)
#include <cuda_runtime.h>
#include <cuda_bf16.h>
#include <math.h>

// ---------------- problem constants ----------------
#define BB   2
#define NN   2048
#define CC   1024
#define HH   16
#define DD   64
#define FF   4096
#define ROWS (BB*NN)          // 4096

// ---------------- scratch (device globals; allocation-free) ----------------
__device__ float g_xn[(size_t)ROWS * CC];           // 16 MB (LN1 out, reused for LN2 out)
__device__ float g_q [(size_t)ROWS * CC];           // 16 MB
__device__ float g_k [(size_t)ROWS * CC];           // 16 MB
__device__ float g_v [(size_t)ROWS * CC];           // 16 MB
__device__ float g_s [(size_t)BB * HH * NN * NN];   // 512 MB attention scores
__device__ float g_y [(size_t)ROWS * CC];           // 16 MB
__device__ float g_x1[(size_t)ROWS * CC];           // 16 MB (post-attn residual)
__device__ float g_h [(size_t)ROWS * FF];           // 64 MB MLP hidden

// ---------------- block reductions ----------------
__device__ __forceinline__ float blockReduceSum(float val) {
    __shared__ float sh[33];
    int lane = threadIdx.x & 31, wid = threadIdx.x >> 5;
    #pragma unroll
    for (int o = 16; o; o >>= 1) val += __shfl_xor_sync(0xffffffffu, val, o);
    if (!lane) sh[wid] = val;
    __syncthreads();
    int nw = blockDim.x >> 5;
    if (wid == 0) {
        float v = (lane < nw) ? sh[lane] : 0.f;
        #pragma unroll
        for (int o = 16; o; o >>= 1) v += __shfl_xor_sync(0xffffffffu, v, o);
        if (!lane) sh[32] = v;
    }
    __syncthreads();
    float r = sh[32];
    __syncthreads();
    return r;
}

__device__ __forceinline__ float blockReduceMax(float val) {
    __shared__ float sh[33];
    int lane = threadIdx.x & 31, wid = threadIdx.x >> 5;
    #pragma unroll
    for (int o = 16; o; o >>= 1) val = fmaxf(val, __shfl_xor_sync(0xffffffffu, val, o));
    if (!lane) sh[wid] = val;
    __syncthreads();
    int nw = blockDim.x >> 5;
    if (wid == 0) {
        float v = (lane < nw) ? sh[lane] : -INFINITY;
        #pragma unroll
        for (int o = 16; o; o >>= 1) v = fmaxf(v, __shfl_xor_sync(0xffffffffu, v, o));
        if (!lane) sh[32] = v;
    }
    __syncthreads();
    float r = sh[32];
    __syncthreads();
    return r;
}

// ---------------- LayerNorm: one block per row of 1024 ----------------
__global__ __launch_bounds__(256) void ln_kernel(const float* __restrict__ x,
                                                 const float* __restrict__ gamma,
                                                 const float* __restrict__ beta,
                                                 float* __restrict__ out) {
    const size_t roff = (size_t)blockIdx.x * CC;
    const float4 v = ((const float4*)(x + roff))[threadIdx.x];
    float s = v.x + v.y + v.z + v.w;
    float mu = blockReduceSum(s) * (1.0f / CC);
    float dx = v.x - mu, dy = v.y - mu, dz = v.z - mu, dw = v.w - mu;
    float ss = dx*dx + dy*dy + dz*dz + dw*dw;
    float var = blockReduceSum(ss) * (1.0f / CC);
    float rstd = rsqrtf(var + 1e-6f);
    float4 g = ((const float4*)gamma)[threadIdx.x];
    float4 b = ((const float4*)beta)[threadIdx.x];
    float4 o;
    o.x = dx * rstd * g.x + b.x;
    o.y = dy * rstd * g.y + b.y;
    o.z = dz * rstd * g.z + b.z;
    o.w = dw * rstd * g.w + b.w;
    ((float4*)(out + roff))[threadIdx.x] = o;
}

// ---------------- Softmax: one block per row of 2048 ----------------
__global__ __launch_bounds__(256) void softmax_kernel(float* __restrict__ S) {
    float* row = S + (size_t)blockIdx.x * NN;
    float4* row4 = (float4*)row;
    float4 a = row4[threadIdx.x];
    float4 b = row4[threadIdx.x + 256];
    float m = fmaxf(fmaxf(fmaxf(a.x, a.y), fmaxf(a.z, a.w)),
                    fmaxf(fmaxf(b.x, b.y), fmaxf(b.z, b.w)));
    m = blockReduceMax(m);
    a.x = __expf(a.x - m); a.y = __expf(a.y - m); a.z = __expf(a.z - m); a.w = __expf(a.w - m);
    b.x = __expf(b.x - m); b.y = __expf(b.y - m); b.z = __expf(b.z - m); b.w = __expf(b.w - m);
    float s = a.x + a.y + a.z + a.w + b.x + b.y + b.z + b.w;
    s = blockReduceSum(s);
    float inv = 1.0f / s;
    a.x *= inv; a.y *= inv; a.z *= inv; a.w *= inv;
    b.x *= inv; b.y *= inv; b.z *= inv; b.w *= inv;
    row4[threadIdx.x] = a;
    row4[threadIdx.x + 256] = b;
}

// ---------------- Generic tiled SGEMM ----------------
// C[m][n] = epi( alpha * sum_k A[m*lda+k] * (TB ? B[n*ldb+k] : B[k*ldb+n]) )
// Batched: z -> (b = z/H, h = z%H); pointer offsets b*bs + h*hs for A/B/C.
// EPI: 0 = plain; 1 = + bias[n] + resid[m*ldc+n]; 2 = gelu(acc + bias[n])
template<int BM, int BN, int BK, int TM, int TN, bool TB, int EPI>
__global__ __launch_bounds__((BM/TM)*(BN/TN)) void gemm_kernel(
    const float* __restrict__ A, const float* __restrict__ B, float* __restrict__ C,
    const float* __restrict__ bias, const float* __restrict__ resid,
    int M, int N, int K, int lda, int ldb, int ldc,
    long bsA, long hsA, long bsB, long hsB, long bsC, long hsC,
    int H, float alpha)
{
    constexpr int NT = (BM/TM)*(BN/TN);
    const int z = blockIdx.z;
    const int bz = z / H, hz = z % H;
    A += (long)bz * bsA + (long)hz * hsA;
    B += (long)bz * bsB + (long)hz * hsB;
    C += (long)bz * bsC + (long)hz * hsC;

    __shared__ float As[BK][BM];
    __shared__ float Bs[BK][BN];

    const int tid  = threadIdx.x;
    const int row0 = blockIdx.y * BM;
    const int col0 = blockIdx.x * BN;

    // A (and TB-B) load mapping: float4 along k
    constexpr int AV = BK / 4;             // float4 per k-row
    constexpr int AROWS = NT / AV;         // rows loaded per iteration
    const int a_row = tid / AV;
    const int a_col = (tid % AV) * 4;
    // non-TB B load mapping: float4 along n
    constexpr int BVn = BN / 4;
    constexpr int BROWS = NT / BVn;
    const int b_row = tid / BVn;
    const int b_col = (tid % BVn) * 4;

    const int tr = (tid / (BN/TN)) * TM;   // local row base
    const int tc = (tid % (BN/TN)) * TN;   // local col base

    float acc[TM][TN];
    #pragma unroll
    for (int i = 0; i < TM; i++)
        #pragma unroll
        for (int j = 0; j < TN; j++) acc[i][j] = 0.f;

    for (int k0 = 0; k0 < K; k0 += BK) {
        // load A tile (transposed into As[k][m])
        #pragma unroll
        for (int it = 0; it < BM / AROWS; it++) {
            int r = a_row + it * AROWS;
            float4 v = *(const float4*)&A[(long)(row0 + r) * lda + (k0 + a_col)];
            As[a_col + 0][r] = v.x; As[a_col + 1][r] = v.y;
            As[a_col + 2][r] = v.z; As[a_col + 3][r] = v.w;
        }
        if (TB) {
            #pragma unroll
            for (int it = 0; it < BN / AROWS; it++) {
                int r = a_row + it * AROWS;
                float4 v = *(const float4*)&B[(long)(col0 + r) * ldb + (k0 + a_col)];
                Bs[a_col + 0][r] = v.x; Bs[a_col + 1][r] = v.y;
                Bs[a_col + 2][r] = v.z; Bs[a_col + 3][r] = v.w;
            }
        } else {
            #pragma unroll
            for (int it = 0; it < BK / BROWS; it++) {
                int r = b_row + it * BROWS;
                float4 v = *(const float4*)&B[(long)(k0 + r) * ldb + (col0 + b_col)];
                *(float4*)&Bs[r][b_col] = v;
            }
        }
        __syncthreads();

        #pragma unroll
        for (int kk = 0; kk < BK; kk++) {
            float ra[TM], rb[TN];
            #pragma unroll
            for (int i = 0; i < TM; i++) ra[i] = As[kk][tr + i];
            #pragma unroll
            for (int j = 0; j < TN; j++) rb[j] = Bs[kk][tc + j];
            #pragma unroll
            for (int i = 0; i < TM; i++)
                #pragma unroll
                for (int j = 0; j < TN; j++)
                    acc[i][j] = fmaf(ra[i], rb[j], acc[i][j]);
        }
        __syncthreads();
    }

    // epilogue
    #pragma unroll
    for (int i = 0; i < TM; i++) {
        const int gm = row0 + tr + i;
        #pragma unroll
        for (int j = 0; j < TN; j++) {
            const int gn = col0 + tc + j;
            float v = acc[i][j] * alpha;
            if (EPI == 1) {
                v += bias[gn] + resid[(long)gm * ldc + gn];
            } else if (EPI == 2) {
                v += bias[gn];
                v = 0.5f * v * (1.0f + erff(v * 0.70710678118654752f)); // exact GELU
            }
            C[(long)gm * ldc + gn] = v;
        }
    }
}

// ---------------- launch ----------------
extern "C" void kernel_launch(void* const* d_in, const int* in_sizes, int n_in,
                              void* d_out, int out_size) {
    const float* x      = (const float*)d_in[0];
    const float* Wq     = (const float*)d_in[1];
    const float* Wk     = (const float*)d_in[2];
    const float* Wv     = (const float*)d_in[3];
    const float* Wp     = (const float*)d_in[4];
    const float* bp     = (const float*)d_in[5];
    const float* W1     = (const float*)d_in[6];
    const float* b1     = (const float*)d_in[7];
    const float* W2     = (const float*)d_in[8];
    const float* b2     = (const float*)d_in[9];
    const float* gamma1 = (const float*)d_in[10];
    const float* beta1  = (const float*)d_in[11];
    const float* gamma2 = (const float*)d_in[12];
    const float* beta2  = (const float*)d_in[13];
    float* out = (float*)d_out;

    float *xn, *q, *k, *v, *S, *y, *x1, *hbuf;
    cudaGetSymbolAddress((void**)&xn,   g_xn);
    cudaGetSymbolAddress((void**)&q,    g_q);
    cudaGetSymbolAddress((void**)&k,    g_k);
    cudaGetSymbolAddress((void**)&v,    g_v);
    cudaGetSymbolAddress((void**)&S,    g_s);
    cudaGetSymbolAddress((void**)&y,    g_y);
    cudaGetSymbolAddress((void**)&x1,   g_x1);
    cudaGetSymbolAddress((void**)&hbuf, g_h);

    const float qscale = 0.125f; // D^-0.5 = 64^-0.5

    // 1) LN1
    ln_kernel<<<ROWS, 256>>>(x, gamma1, beta1, xn);

    // 2) QKV projections: [4096,1024] @ [1024,1024]
    gemm_kernel<128,128,16,8,8,false,0><<<dim3(CC/128, ROWS/128, 1), 256>>>(
        xn, Wq, q, nullptr, nullptr, ROWS, CC, CC, CC, CC, CC,
        0,0,0,0,0,0, 1, qscale);
    gemm_kernel<128,128,16,8,8,false,0><<<dim3(CC/128, ROWS/128, 1), 256>>>(
        xn, Wk, k, nullptr, nullptr, ROWS, CC, CC, CC, CC, CC,
        0,0,0,0,0,0, 1, 1.0f);
    gemm_kernel<128,128,16,8,8,false,0><<<dim3(CC/128, ROWS/128, 1), 256>>>(
        xn, Wv, v, nullptr, nullptr, ROWS, CC, CC, CC, CC, CC,
        0,0,0,0,0,0, 1, 1.0f);

    // 3) S = Q @ K^T per (b,h): M=N=2048, K=64; batched over z = b*H + h
    gemm_kernel<128,128,16,8,8,true,0><<<dim3(NN/128, NN/128, BB*HH), 256>>>(
        q, k, S, nullptr, nullptr, NN, NN, DD, CC, CC, NN,
        (long)NN*CC, (long)DD,           // A (q): per-b, per-h
        (long)NN*CC, (long)DD,           // B (k)
        (long)HH*NN*NN, (long)NN*NN,     // C (S)
        HH, 1.0f);

    // 4) softmax rows of S
    softmax_kernel<<<BB*HH*NN, 256>>>(S);

    // 5) Y = S @ V per (b,h): M=2048, N=64, K=2048
    gemm_kernel<128,64,16,8,4,false,0><<<dim3(1, NN/128, BB*HH), 256>>>(
        S, v, y, nullptr, nullptr, NN, DD, NN, NN, CC, CC,
        (long)HH*NN*NN, (long)NN*NN,     // A (S)
        (long)NN*CC, (long)DD,           // B (v)
        (long)NN*CC, (long)DD,           // C (y)
        HH, 1.0f);

    // 6) x1 = x + y @ Wp + bp
    gemm_kernel<128,128,16,8,8,false,1><<<dim3(CC/128, ROWS/128, 1), 256>>>(
        y, Wp, x1, bp, x, ROWS, CC, CC, CC, CC, CC,
        0,0,0,0,0,0, 1, 1.0f);

    // 7) LN2
    ln_kernel<<<ROWS, 256>>>(x1, gamma2, beta2, xn);

    // 8) h = gelu(xn @ W1 + b1): [4096,1024] @ [1024,4096]
    gemm_kernel<128,128,16,8,8,false,2><<<dim3(FF/128, ROWS/128, 1), 256>>>(
        xn, W1, hbuf, b1, nullptr, ROWS, FF, CC, CC, FF, FF,
        0,0,0,0,0,0, 1, 1.0f);

    // 9) out = x1 + h @ W2 + b2: [4096,4096] @ [4096,1024]
    gemm_kernel<128,128,16,8,8,false,1><<<dim3(CC/128, ROWS/128, 1), 256>>>(
        hbuf, W2, out, b2, x1, ROWS, CC, FF, FF, CC, CC,
        0,0,0,0,0,0, 1, 1.0f);
}

// round 7
// speedup vs baseline: 4.9997x; 4.9997x over previous
#include <cuda_runtime.h>
#include <cuda_fp16.h>
#include <cstdint>
#include <math.h>

// ---------------- problem constants ----------------
#define BB   2
#define NN   2048
#define CC   1024
#define HH   16
#define DD   64
#define FF   4096
#define ROWS (BB*NN)          // 4096

// ---------------- scratch (device globals; allocation-free) ----------------
__device__ __half g_xnh [(size_t)ROWS * CC];
__device__ __half g_qh  [(size_t)ROWS * CC];
__device__ __half g_kh  [(size_t)ROWS * CC];
__device__ __half g_vh  [(size_t)ROWS * CC];
__device__ __half g_vth [(size_t)ROWS * CC];          // per-head V^T [z][d][n]
__device__ __half g_sh  [(size_t)BB * HH * NN * NN];  // 256 MB fp16 scores
__device__ __half g_yh  [(size_t)ROWS * CC];
__device__ float  g_x1  [(size_t)ROWS * CC];          // fp32 post-attn residual
__device__ __half g_hh  [(size_t)ROWS * FF];
__device__ __half g_wqT [(size_t)CC * CC];
__device__ __half g_wkT [(size_t)CC * CC];
__device__ __half g_wvT [(size_t)CC * CC];
__device__ __half g_wpT [(size_t)CC * CC];
__device__ __half g_w1T [(size_t)CC * FF];
__device__ __half g_w2T [(size_t)CC * FF];

// ---------------- PTX helpers ----------------
__device__ __forceinline__ uint32_t smem_u32(const void* p) {
    uint32_t a;
    asm("{ .reg .u64 t; cvta.to.shared.u64 t, %1; cvt.u32.u64 %0, t; }" : "=r"(a) : "l"(p));
    return a;
}
#define SW128(off) ((off) ^ (((off) >> 3) & 0x70))

__device__ __forceinline__ void cp16(uint32_t s, const void* g) {
    asm volatile("cp.async.cg.shared.global [%0], [%1], 16;" :: "r"(s), "l"(g));
}
#define CP_COMMIT() asm volatile("cp.async.commit_group;" ::: "memory")
#define CP_WAIT2()  asm volatile("cp.async.wait_group 2;" ::: "memory")

__device__ __forceinline__ void ldsm4(uint32_t& r0, uint32_t& r1, uint32_t& r2, uint32_t& r3,
                                      uint32_t addr) {
    asm volatile("ldmatrix.sync.aligned.m8n8.x4.shared.b16 {%0,%1,%2,%3}, [%4];"
                 : "=r"(r0), "=r"(r1), "=r"(r2), "=r"(r3) : "r"(addr));
}

__device__ __forceinline__ void mma16816(float* c, const uint32_t* a, uint32_t b0, uint32_t b1) {
    asm volatile("mma.sync.aligned.m16n8k16.row.col.f32.f16.f16.f32 "
                 "{%0,%1,%2,%3}, {%4,%5,%6,%7}, {%8,%9}, {%0,%1,%2,%3};"
                 : "+f"(c[0]), "+f"(c[1]), "+f"(c[2]), "+f"(c[3])
                 : "r"(a[0]), "r"(a[1]), "r"(a[2]), "r"(a[3]), "r"(b0), "r"(b1));
}

// ---------------- fp16 tensor-core GEMM ----------------
// C[m][n] = epi(alpha * sum_k A[m][k] * B[n][k]);  A:[M,K] lda, B:[N,K] ldb, fp16 K-major.
// EPI: 0 plain, 1 +bias[n]+resid[m][n] (fp32), 2 gelu(acc+bias[n]).  OUTH: fp16 vs fp32 out.
// batched over blockIdx.z -> (bz=z/H, hz=z%H)
template<int BN, int EPI, bool OUTH>
__global__ void __launch_bounds__(256) hgemm(
    const __half* __restrict__ A, const __half* __restrict__ Bm, void* __restrict__ Cv,
    const float* __restrict__ bias, const float* __restrict__ resid,
    int K, int lda, int ldb, int ldc,
    long bsA, long hsA, long bsB, long hsB, long bsC, long hsC,
    int H, float alpha)
{
    constexpr int BM = 128, BK = 64;
    constexpr int ABYTES = BM * BK * 2;   // 16384
    constexpr int BBYTES = BN * BK * 2;
    constexpr int WN   = BN / 4;          // warp tile n (32 or 16)
    constexpr int NB16 = WN / 16;         // n16 blocks per warp (2 or 1)

    extern __shared__ char smraw[];
    const uint32_t su  = (smem_u32(smraw) + 1023) & ~1023u;
    const uint32_t suA = su;
    const uint32_t suB = su + 3 * ABYTES;

    const int tid = threadIdx.x, wid = tid >> 5, lane = tid & 31;
    const int z = blockIdx.z, bz = z / H, hz = z % H;
    A  += (size_t)bz * bsA + (size_t)hz * hsA;
    Bm += (size_t)bz * bsB + (size_t)hz * hsB;

    const int row0 = blockIdx.y * BM;
    const int col0 = blockIdx.x * BN;
    const __half* Abase = A  + (size_t)row0 * lda;
    const __half* Bbase = Bm + (size_t)col0 * ldb;

    const int wm = (wid >> 2) * 64;       // warp row offset (2 warp-rows)
    const int wn = (wid & 3) * WN;        // warp col offset (4 warp-cols)

    float acc[4][NB16 * 2][4];
    #pragma unroll
    for (int i = 0; i < 4; i++)
        #pragma unroll
        for (int j = 0; j < NB16 * 2; j++)
            #pragma unroll
            for (int q = 0; q < 4; q++) acc[i][j][q] = 0.f;

    const int ntiles = K >> 6;

    // ---- tile loaders ----
    auto loadA = [&](int tile, int stg) {
        const __half* src = Abase + tile * BK;
        uint32_t dst = suA + stg * ABYTES;
        #pragma unroll
        for (int j = 0; j < 4; j++) {
            int c = tid + j * 256;
            int r = c >> 3, a = c & 7;
            cp16(dst + SW128(r * 128 + a * 16), src + (size_t)r * lda + a * 8);
        }
    };
    auto loadB = [&](int tile, int stg) {
        const __half* src = Bbase + tile * BK;
        uint32_t dst = suB + stg * BBYTES;
        #pragma unroll
        for (int j = 0; j < BN / 32; j++) {
            int c = tid + j * 256;
            int r = c >> 3, a = c & 7;
            cp16(dst + SW128(r * 128 + a * 16), src + (size_t)r * ldb + a * 8);
        }
    };

    // prologue: always commit 2 groups
    #pragma unroll
    for (int t = 0; t < 2; t++) {
        if (t < ntiles) { loadA(t, t); loadB(t, t); }
        CP_COMMIT();
    }

    for (int i = 0; i < ntiles; i++) {
        const int nt = i + 2;
        if (nt < ntiles) { loadA(nt, nt % 3); loadB(nt, nt % 3); }
        CP_COMMIT();
        CP_WAIT2();
        __syncthreads();

        const uint32_t sa = suA + (i % 3) * ABYTES;
        const uint32_t sb = suB + (i % 3) * BBYTES;
        #pragma unroll
        for (int ks = 0; ks < 4; ks++) {
            uint32_t af[4][4];
            #pragma unroll
            for (int mi = 0; mi < 4; mi++) {
                int row  = wm + mi * 16 + (lane & 15);
                int byte = ks * 32 + ((lane >> 4) << 4);
                ldsm4(af[mi][0], af[mi][1], af[mi][2], af[mi][3],
                      sa + SW128(row * 128 + byte));
            }
            uint32_t bf[NB16][4];
            #pragma unroll
            for (int ni = 0; ni < NB16; ni++) {
                int row  = wn + ni * 16 + ((lane >> 4) << 3) + (lane & 7);
                int byte = ks * 32 + (((lane >> 3) & 1) << 4);
                ldsm4(bf[ni][0], bf[ni][1], bf[ni][2], bf[ni][3],
                      sb + SW128(row * 128 + byte));
            }
            #pragma unroll
            for (int mi = 0; mi < 4; mi++)
                #pragma unroll
                for (int ni = 0; ni < NB16; ni++) {
                    mma16816(acc[mi][ni * 2 + 0], af[mi], bf[ni][0], bf[ni][1]);
                    mma16816(acc[mi][ni * 2 + 1], af[mi], bf[ni][2], bf[ni][3]);
                }
        }
        __syncthreads();
    }

    // ---- epilogue ----
    float*  Cf = (float*)Cv;
    __half* Ch = (__half*)Cv;
    const size_t coff = (size_t)bz * bsC + (size_t)hz * hsC;

    #pragma unroll
    for (int mi = 0; mi < 4; mi++) {
        #pragma unroll
        for (int nj = 0; nj < NB16 * 2; nj++) {
            const float* c = acc[mi][nj];
            const int gc = col0 + wn + nj * 8 + ((lane & 3) << 1);
            #pragma unroll
            for (int s = 0; s < 2; s++) {
                const int gr = row0 + wm + mi * 16 + (lane >> 2) + 8 * s;
                float v0 = c[2 * s + 0] * alpha;
                float v1 = c[2 * s + 1] * alpha;
                if (EPI == 1) {
                    v0 += bias[gc + 0] + resid[(size_t)gr * ldc + gc + 0];
                    v1 += bias[gc + 1] + resid[(size_t)gr * ldc + gc + 1];
                } else if (EPI == 2) {
                    v0 += bias[gc + 0];
                    v1 += bias[gc + 1];
                    v0 = 0.5f * v0 * (1.0f + erff(v0 * 0.70710678118654752f));
                    v1 = 0.5f * v1 * (1.0f + erff(v1 * 0.70710678118654752f));
                }
                if (OUTH) {
                    *(__half2*)&Ch[coff + (size_t)gr * ldc + gc] = __floats2half2_rn(v0, v1);
                } else {
                    *(float2*)&Cf[coff + (size_t)gr * ldc + gc] = make_float2(v0, v1);
                }
            }
        }
    }
}

// ---------------- transposes ----------------
// fp32 in [R,C] -> fp16 out [C,R]
__global__ void __launch_bounds__(256) transpose_f2h(
    const float* __restrict__ in, __half* __restrict__ out, int ldi, int ldo)
{
    __shared__ float t[32][33];
    const int r0 = blockIdx.y * 32, c0 = blockIdx.x * 32;
    const int tx = threadIdx.x & 31, ty = threadIdx.x >> 5;
    #pragma unroll
    for (int i = ty; i < 32; i += 8)
        t[i][tx] = in[(size_t)(r0 + i) * ldi + c0 + tx];
    __syncthreads();
    #pragma unroll
    for (int i = ty; i < 32; i += 8)
        out[(size_t)(c0 + i) * ldo + r0 + tx] = __float2half(t[tx][i]);
}

// fp16 in -> fp16 out, batched per (b,h): v[b][n][h*64+d] -> vt[z][d][n]
__global__ void __launch_bounds__(256) transpose_h2h(
    const __half* __restrict__ in, __half* __restrict__ out,
    int ldi, int ldo, long bsi, long hsi, long bso, long hso, int H)
{
    __shared__ __half t[32][34];
    const int z = blockIdx.z, bz = z / H, hz = z % H;
    in  += (size_t)bz * bsi + (size_t)hz * hsi;
    out += (size_t)bz * bso + (size_t)hz * hso;
    const int r0 = blockIdx.y * 32, c0 = blockIdx.x * 32;
    const int tx = threadIdx.x & 31, ty = threadIdx.x >> 5;
    #pragma unroll
    for (int i = ty; i < 32; i += 8)
        t[i][tx] = in[(size_t)(r0 + i) * ldi + c0 + tx];
    __syncthreads();
    #pragma unroll
    for (int i = ty; i < 32; i += 8)
        out[(size_t)(c0 + i) * ldo + r0 + tx] = t[tx][i];
}

// ---------------- block reductions ----------------
__device__ __forceinline__ float blockReduceSum(float val) {
    __shared__ float sh[33];
    int lane = threadIdx.x & 31, wid = threadIdx.x >> 5;
    #pragma unroll
    for (int o = 16; o; o >>= 1) val += __shfl_xor_sync(0xffffffffu, val, o);
    if (!lane) sh[wid] = val;
    __syncthreads();
    int nw = blockDim.x >> 5;
    if (wid == 0) {
        float v = (lane < nw) ? sh[lane] : 0.f;
        #pragma unroll
        for (int o = 16; o; o >>= 1) v += __shfl_xor_sync(0xffffffffu, v, o);
        if (!lane) sh[32] = v;
    }
    __syncthreads();
    float r = sh[32];
    __syncthreads();
    return r;
}
__device__ __forceinline__ float blockReduceMax(float val) {
    __shared__ float sh[33];
    int lane = threadIdx.x & 31, wid = threadIdx.x >> 5;
    #pragma unroll
    for (int o = 16; o; o >>= 1) val = fmaxf(val, __shfl_xor_sync(0xffffffffu, val, o));
    if (!lane) sh[wid] = val;
    __syncthreads();
    int nw = blockDim.x >> 5;
    if (wid == 0) {
        float v = (lane < nw) ? sh[lane] : -INFINITY;
        #pragma unroll
        for (int o = 16; o; o >>= 1) v = fmaxf(v, __shfl_xor_sync(0xffffffffu, v, o));
        if (!lane) sh[32] = v;
    }
    __syncthreads();
    float r = sh[32];
    __syncthreads();
    return r;
}

// ---------------- LayerNorm (fp32 in -> fp16 out) ----------------
__global__ __launch_bounds__(256) void ln_h(const float* __restrict__ x,
                                            const float* __restrict__ gamma,
                                            const float* __restrict__ beta,
                                            __half* __restrict__ out) {
    const size_t roff = (size_t)blockIdx.x * CC;
    const float4 v = ((const float4*)(x + roff))[threadIdx.x];
    float mu = blockReduceSum(v.x + v.y + v.z + v.w) * (1.0f / CC);
    float dx = v.x - mu, dy = v.y - mu, dz = v.z - mu, dw = v.w - mu;
    float var = blockReduceSum(dx*dx + dy*dy + dz*dz + dw*dw) * (1.0f / CC);
    float rstd = rsqrtf(var + 1e-6f);
    float4 g = ((const float4*)gamma)[threadIdx.x];
    float4 b = ((const float4*)beta)[threadIdx.x];
    __half2* o2 = (__half2*)(out + roff);
    o2[2 * threadIdx.x + 0] = __floats2half2_rn(dx*rstd*g.x + b.x, dy*rstd*g.y + b.y);
    o2[2 * threadIdx.x + 1] = __floats2half2_rn(dz*rstd*g.z + b.z, dw*rstd*g.w + b.w);
}

// ---------------- Softmax over fp16 rows of 2048 ----------------
__global__ __launch_bounds__(256) void softmax_h(__half* __restrict__ S) {
    uint4* row = (uint4*)(S + (size_t)blockIdx.x * NN);
    uint4 u = row[threadIdx.x];           // 8 halves
    __half2* ph = (__half2*)&u;
    float f[8];
    #pragma unroll
    for (int i = 0; i < 4; i++) {
        float2 p = __half22float2(ph[i]);
        f[2*i] = p.x; f[2*i+1] = p.y;
    }
    float m = f[0];
    #pragma unroll
    for (int i = 1; i < 8; i++) m = fmaxf(m, f[i]);
    m = blockReduceMax(m);
    float s = 0.f;
    #pragma unroll
    for (int i = 0; i < 8; i++) { f[i] = __expf(f[i] - m); s += f[i]; }
    s = blockReduceSum(s);
    float inv = 1.0f / s;
    #pragma unroll
    for (int i = 0; i < 4; i++)
        ph[i] = __floats2half2_rn(f[2*i] * inv, f[2*i+1] * inv);
    row[threadIdx.x] = u;
}

// ---------------- launch ----------------
extern "C" void kernel_launch(void* const* d_in, const int* in_sizes, int n_in,
                              void* d_out, int out_size) {
    const float* x      = (const float*)d_in[0];
    const float* Wq     = (const float*)d_in[1];
    const float* Wk     = (const float*)d_in[2];
    const float* Wv     = (const float*)d_in[3];
    const float* Wp     = (const float*)d_in[4];
    const float* bp     = (const float*)d_in[5];
    const float* W1     = (const float*)d_in[6];
    const float* b1     = (const float*)d_in[7];
    const float* W2     = (const float*)d_in[8];
    const float* b2     = (const float*)d_in[9];
    const float* gamma1 = (const float*)d_in[10];
    const float* beta1  = (const float*)d_in[11];
    const float* gamma2 = (const float*)d_in[12];
    const float* beta2  = (const float*)d_in[13];
    float* out = (float*)d_out;

    __half *xnh,*qh,*kh,*vh,*vth,*Sh,*yh,*hh,*wqT,*wkT,*wvT,*wpT,*w1T,*w2T;
    float *x1;
    cudaGetSymbolAddress((void**)&xnh, g_xnh); cudaGetSymbolAddress((void**)&qh, g_qh);
    cudaGetSymbolAddress((void**)&kh, g_kh);   cudaGetSymbolAddress((void**)&vh, g_vh);
    cudaGetSymbolAddress((void**)&vth, g_vth); cudaGetSymbolAddress((void**)&Sh, g_sh);
    cudaGetSymbolAddress((void**)&yh, g_yh);   cudaGetSymbolAddress((void**)&x1, g_x1);
    cudaGetSymbolAddress((void**)&hh, g_hh);
    cudaGetSymbolAddress((void**)&wqT, g_wqT); cudaGetSymbolAddress((void**)&wkT, g_wkT);
    cudaGetSymbolAddress((void**)&wvT, g_wvT); cudaGetSymbolAddress((void**)&wpT, g_wpT);
    cudaGetSymbolAddress((void**)&w1T, g_w1T); cudaGetSymbolAddress((void**)&w2T, g_w2T);

    const int SM128 = 1024 + 3 * 16384 + 3 * 16384;  // 99328
    const int SM64  = 1024 + 3 * 16384 + 3 * 8192;   // 74752
    cudaFuncSetAttribute(hgemm<128,0,true >, cudaFuncAttributeMaxDynamicSharedMemorySize, SM128);
    cudaFuncSetAttribute(hgemm<128,1,false>, cudaFuncAttributeMaxDynamicSharedMemorySize, SM128);
    cudaFuncSetAttribute(hgemm<128,2,true >, cudaFuncAttributeMaxDynamicSharedMemorySize, SM128);
    cudaFuncSetAttribute(hgemm<64, 0,true >, cudaFuncAttributeMaxDynamicSharedMemorySize, SM64);

    dim3 t256(256);

    // 0) weight transposes + fp16 convert: W[K,N] -> WT[N,K]
    transpose_f2h<<<dim3(CC/32, CC/32), t256>>>(Wq, wqT, CC, CC);
    transpose_f2h<<<dim3(CC/32, CC/32), t256>>>(Wk, wkT, CC, CC);
    transpose_f2h<<<dim3(CC/32, CC/32), t256>>>(Wv, wvT, CC, CC);
    transpose_f2h<<<dim3(CC/32, CC/32), t256>>>(Wp, wpT, CC, CC);
    transpose_f2h<<<dim3(FF/32, CC/32), t256>>>(W1, w1T, FF, CC);
    transpose_f2h<<<dim3(CC/32, FF/32), t256>>>(W2, w2T, CC, FF);

    // 1) LN1 -> fp16
    ln_h<<<ROWS, 256>>>(x, gamma1, beta1, xnh);

    // 2) QKV projections (q pre-scaled by D^-0.5)
    hgemm<128,0,true><<<dim3(CC/128, ROWS/128, 1), t256, SM128>>>(
        xnh, wqT, qh, nullptr, nullptr, CC, CC, CC, CC, 0,0,0,0,0,0, 1, 0.125f);
    hgemm<128,0,true><<<dim3(CC/128, ROWS/128, 1), t256, SM128>>>(
        xnh, wkT, kh, nullptr, nullptr, CC, CC, CC, CC, 0,0,0,0,0,0, 1, 1.0f);
    hgemm<128,0,true><<<dim3(CC/128, ROWS/128, 1), t256, SM128>>>(
        xnh, wvT, vh, nullptr, nullptr, CC, CC, CC, CC, 0,0,0,0,0,0, 1, 1.0f);

    // 3) per-head V transpose: v[b][n][h*64+d] -> vt[z][d][n]
    transpose_h2h<<<dim3(DD/32, NN/32, BB*HH), t256>>>(
        vh, vth, CC, NN, (long)NN*CC, (long)DD, (long)HH*DD*NN, (long)DD*NN, HH);

    // 4) S = Q @ K^T per (b,h)
    hgemm<128,0,true><<<dim3(NN/128, NN/128, BB*HH), t256, SM128>>>(
        qh, kh, Sh, nullptr, nullptr, DD, CC, CC, NN,
        (long)NN*CC, (long)DD, (long)NN*CC, (long)DD,
        (long)HH*NN*NN, (long)NN*NN, HH, 1.0f);

    // 5) softmax
    softmax_h<<<BB*HH*NN, 256>>>(Sh);

    // 6) Y = S @ V
    hgemm<64,0,true><<<dim3(1, NN/128, BB*HH), t256, SM64>>>(
        Sh, vth, yh, nullptr, nullptr, NN, NN, NN, CC,
        (long)HH*NN*NN, (long)NN*NN, (long)HH*DD*NN, (long)DD*NN,
        (long)NN*CC, (long)DD, HH, 1.0f);

    // 7) x1 = x + y @ Wp + bp   (fp32 out)
    hgemm<128,1,false><<<dim3(CC/128, ROWS/128, 1), t256, SM128>>>(
        yh, wpT, x1, bp, x, CC, CC, CC, CC, 0,0,0,0,0,0, 1, 1.0f);

    // 8) LN2 -> fp16
    ln_h<<<ROWS, 256>>>(x1, gamma2, beta2, xnh);

    // 9) h = gelu(xn @ W1 + b1)
    hgemm<128,2,true><<<dim3(FF/128, ROWS/128, 1), t256, SM128>>>(
        xnh, w1T, hh, b1, nullptr, CC, CC, CC, FF, 0,0,0,0,0,0, 1, 1.0f);

    // 10) out = x1 + h @ W2 + b2  (fp32 out)
    hgemm<128,1,false><<<dim3(CC/128, ROWS/128, 1), t256, SM128>>>(
        hh, w2T, out, b2, x1, FF, FF, FF, CC, 0,0,0,0,0,0, 1, 1.0f);
}

// round 14
// speedup vs baseline: 6.9652x; 1.3931x over previous
#include <cuda_runtime.h>
#include <cuda_fp16.h>
#include <cstdint>
#include <math.h>

// ---------------- problem constants ----------------
#define BB   2
#define NN   2048
#define CC   1024
#define HH   16
#define DD   64
#define FF   4096
#define ROWS (BB*NN)          // 4096

// ---------------- scratch (device globals; allocation-free) ----------------
__device__ __half g_xnh [(size_t)ROWS * CC];
__device__ __half g_qh  [(size_t)ROWS * CC];
__device__ __half g_kh  [(size_t)ROWS * CC];
__device__ __half g_vh  [(size_t)ROWS * CC];
__device__ __half g_vth [(size_t)ROWS * CC];          // per-head V^T [z][d][n]
__device__ __half g_yh  [(size_t)ROWS * CC];
__device__ float  g_x1  [(size_t)ROWS * CC];          // fp32 post-attn residual
__device__ __half g_hh  [(size_t)ROWS * FF];
__device__ __half g_wqT [(size_t)CC * CC];
__device__ __half g_wkT [(size_t)CC * CC];
__device__ __half g_wvT [(size_t)CC * CC];
__device__ __half g_wpT [(size_t)CC * CC];
__device__ __half g_w1T [(size_t)CC * FF];
__device__ __half g_w2T [(size_t)CC * FF];

// ---------------- PTX helpers ----------------
__device__ __forceinline__ uint32_t smem_u32(const void* p) {
    uint32_t a;
    asm("{ .reg .u64 t; cvta.to.shared.u64 t, %1; cvt.u32.u64 %0, t; }" : "=r"(a) : "l"(p));
    return a;
}
#define SW128(off) ((off) ^ (((off) >> 3) & 0x70))

__device__ __forceinline__ void cp16(uint32_t s, const void* g) {
    asm volatile("cp.async.cg.shared.global [%0], [%1], 16;" :: "r"(s), "l"(g));
}
#define CP_COMMIT() asm volatile("cp.async.commit_group;" ::: "memory")
#define CP_WAIT2()  asm volatile("cp.async.wait_group 2;" ::: "memory")
#define CP_WAIT1()  asm volatile("cp.async.wait_group 1;" ::: "memory")

__device__ __forceinline__ void ldsm4(uint32_t& r0, uint32_t& r1, uint32_t& r2, uint32_t& r3,
                                      uint32_t addr) {
    asm volatile("ldmatrix.sync.aligned.m8n8.x4.shared.b16 {%0,%1,%2,%3}, [%4];"
                 : "=r"(r0), "=r"(r1), "=r"(r2), "=r"(r3) : "r"(addr));
}

__device__ __forceinline__ void mma16816(float* c, const uint32_t* a, uint32_t b0, uint32_t b1) {
    asm volatile("mma.sync.aligned.m16n8k16.row.col.f32.f16.f16.f32 "
                 "{%0,%1,%2,%3}, {%4,%5,%6,%7}, {%8,%9}, {%0,%1,%2,%3};"
                 : "+f"(c[0]), "+f"(c[1]), "+f"(c[2]), "+f"(c[3])
                 : "r"(a[0]), "r"(a[1]), "r"(a[2]), "r"(a[3]), "r"(b0), "r"(b1));
}
__device__ __forceinline__ uint32_t packh2(float lo, float hi) {
    uint32_t r;
    asm("cvt.rn.f16x2.f32 %0, %1, %2;" : "=r"(r) : "f"(hi), "f"(lo));
    return r;
}

// ---------------- fp16 tensor-core GEMM (unchanged, proven) ----------------
template<int BN, int EPI, bool OUTH>
__global__ void __launch_bounds__(256) hgemm(
    const __half* __restrict__ A, const __half* __restrict__ Bm, void* __restrict__ Cv,
    const float* __restrict__ bias, const float* __restrict__ resid,
    int K, int lda, int ldb, int ldc,
    long bsA, long hsA, long bsB, long hsB, long bsC, long hsC,
    int H, float alpha)
{
    constexpr int BM = 128, BK = 64;
    constexpr int ABYTES = BM * BK * 2;
    constexpr int BBYTES = BN * BK * 2;
    constexpr int WN   = BN / 4;
    constexpr int NB16 = WN / 16;

    extern __shared__ char smraw[];
    const uint32_t su  = (smem_u32(smraw) + 1023) & ~1023u;
    const uint32_t suA = su;
    const uint32_t suB = su + 3 * ABYTES;

    const int tid = threadIdx.x, wid = tid >> 5, lane = tid & 31;
    const int z = blockIdx.z, bz = z / H, hz = z % H;
    A  += (size_t)bz * bsA + (size_t)hz * hsA;
    Bm += (size_t)bz * bsB + (size_t)hz * hsB;

    const int row0 = blockIdx.y * BM;
    const int col0 = blockIdx.x * BN;
    const __half* Abase = A  + (size_t)row0 * lda;
    const __half* Bbase = Bm + (size_t)col0 * ldb;

    const int wm = (wid >> 2) * 64;
    const int wn = (wid & 3) * WN;

    float acc[4][NB16 * 2][4];
    #pragma unroll
    for (int i = 0; i < 4; i++)
        #pragma unroll
        for (int j = 0; j < NB16 * 2; j++)
            #pragma unroll
            for (int q = 0; q < 4; q++) acc[i][j][q] = 0.f;

    const int ntiles = K >> 6;

    auto loadA = [&](int tile, int stg) {
        const __half* src = Abase + tile * BK;
        uint32_t dst = suA + stg * ABYTES;
        #pragma unroll
        for (int j = 0; j < 4; j++) {
            int c = tid + j * 256;
            int r = c >> 3, a = c & 7;
            cp16(dst + SW128(r * 128 + a * 16), src + (size_t)r * lda + a * 8);
        }
    };
    auto loadB = [&](int tile, int stg) {
        const __half* src = Bbase + tile * BK;
        uint32_t dst = suB + stg * BBYTES;
        #pragma unroll
        for (int j = 0; j < BN / 32; j++) {
            int c = tid + j * 256;
            int r = c >> 3, a = c & 7;
            cp16(dst + SW128(r * 128 + a * 16), src + (size_t)r * ldb + a * 8);
        }
    };

    #pragma unroll
    for (int t = 0; t < 2; t++) {
        if (t < ntiles) { loadA(t, t); loadB(t, t); }
        CP_COMMIT();
    }

    for (int i = 0; i < ntiles; i++) {
        const int nt = i + 2;
        if (nt < ntiles) { loadA(nt, nt % 3); loadB(nt, nt % 3); }
        CP_COMMIT();
        CP_WAIT2();
        __syncthreads();

        const uint32_t sa = suA + (i % 3) * ABYTES;
        const uint32_t sb = suB + (i % 3) * BBYTES;
        #pragma unroll
        for (int ks = 0; ks < 4; ks++) {
            uint32_t af[4][4];
            #pragma unroll
            for (int mi = 0; mi < 4; mi++) {
                int row  = wm + mi * 16 + (lane & 15);
                int byte = ks * 32 + ((lane >> 4) << 4);
                ldsm4(af[mi][0], af[mi][1], af[mi][2], af[mi][3],
                      sa + SW128(row * 128 + byte));
            }
            uint32_t bf[NB16][4];
            #pragma unroll
            for (int ni = 0; ni < NB16; ni++) {
                int row  = wn + ni * 16 + ((lane >> 4) << 3) + (lane & 7);
                int byte = ks * 32 + (((lane >> 3) & 1) << 4);
                ldsm4(bf[ni][0], bf[ni][1], bf[ni][2], bf[ni][3],
                      sb + SW128(row * 128 + byte));
            }
            #pragma unroll
            for (int mi = 0; mi < 4; mi++)
                #pragma unroll
                for (int ni = 0; ni < NB16; ni++) {
                    mma16816(acc[mi][ni * 2 + 0], af[mi], bf[ni][0], bf[ni][1]);
                    mma16816(acc[mi][ni * 2 + 1], af[mi], bf[ni][2], bf[ni][3]);
                }
        }
        __syncthreads();
    }

    float*  Cf = (float*)Cv;
    __half* Ch = (__half*)Cv;
    const size_t coff = (size_t)bz * bsC + (size_t)hz * hsC;

    #pragma unroll
    for (int mi = 0; mi < 4; mi++) {
        #pragma unroll
        for (int nj = 0; nj < NB16 * 2; nj++) {
            const float* c = acc[mi][nj];
            const int gc = col0 + wn + nj * 8 + ((lane & 3) << 1);
            #pragma unroll
            for (int s = 0; s < 2; s++) {
                const int gr = row0 + wm + mi * 16 + (lane >> 2) + 8 * s;
                float v0 = c[2 * s + 0] * alpha;
                float v1 = c[2 * s + 1] * alpha;
                if (EPI == 1) {
                    v0 += bias[gc + 0] + resid[(size_t)gr * ldc + gc + 0];
                    v1 += bias[gc + 1] + resid[(size_t)gr * ldc + gc + 1];
                } else if (EPI == 2) {
                    v0 += bias[gc + 0];
                    v1 += bias[gc + 1];
                    v0 = 0.5f * v0 * (1.0f + erff(v0 * 0.70710678118654752f));
                    v1 = 0.5f * v1 * (1.0f + erff(v1 * 0.70710678118654752f));
                }
                if (OUTH) {
                    *(__half2*)&Ch[coff + (size_t)gr * ldc + gc] = __floats2half2_rn(v0, v1);
                } else {
                    *(float2*)&Cf[coff + (size_t)gr * ldc + gc] = make_float2(v0, v1);
                }
            }
        }
    }
}

// ---------------- fused flash attention ----------------
// grid: (NN/128, BB*HH). 8 warps, each owns m16 rows of the 128-row Q tile.
// Streams 128-key K/V tiles (double-buffered cp.async), online softmax in regs,
// P reused directly as MMA A-fragments from the S accumulator layout.
__global__ void __launch_bounds__(256) flash_attn(
    const __half* __restrict__ qh, const __half* __restrict__ kh,
    const __half* __restrict__ vth, __half* __restrict__ yh)
{
    extern __shared__ char smraw[];
    const uint32_t su = (smem_u32(smraw) + 1023) & ~1023u;
    const uint32_t sQ = su;                 // [128][128B]
    const uint32_t sK = su + 16384;         // 2 x [128][128B]
    const uint32_t sV = su + 16384 + 32768; // 2 x (2 x [64][128B])

    const int tid = threadIdx.x, wid = tid >> 5, lane = tid & 31;
    const int z = blockIdx.y, bz = z >> 4, hz = z & 15;
    const int q0 = blockIdx.x * 128;

    const __half* Qg = qh  + (size_t)bz * NN * CC + (size_t)hz * DD;
    const __half* Kg = kh  + (size_t)bz * NN * CC + (size_t)hz * DD;
    const __half* Vg = vth + (size_t)z * DD * NN;

    auto load64 = [&](const __half* src, uint32_t dst) {  // [128 rows][64 halves]
        #pragma unroll
        for (int j = 0; j < 4; j++) {
            int c = tid + j * 256;
            int r = c >> 3, a = c & 7;
            cp16(dst + SW128(r * 128 + a * 16), src + (size_t)r * CC + a * 8);
        }
    };
    auto loadV = [&](int it, uint32_t dst) {  // 2 subtiles [64 d][64 keys]
        #pragma unroll
        for (int j = 0; j < 4; j++) {
            int c = tid + j * 256;
            int r = c >> 3, a = c & 7;
            int sub = r >> 6, rr = r & 63;
            cp16(dst + sub * 8192 + SW128(rr * 128 + a * 16),
                 Vg + (size_t)rr * NN + it * 128 + sub * 64 + a * 8);
        }
    };

    // prologue
    load64(Qg + (size_t)q0 * CC, sQ);
    load64(Kg, sK);
    loadV(0, sV);
    CP_COMMIT();

    const int wm = wid * 16;
    float m0 = -INFINITY, m1 = -INFINITY, l0 = 0.f, l1 = 0.f;
    float oacc[8][4];
    #pragma unroll
    for (int i = 0; i < 8; i++)
        #pragma unroll
        for (int j = 0; j < 4; j++) oacc[i][j] = 0.f;

    for (int it = 0; it < NN / 128; it++) {
        if (it + 1 < NN / 128) {
            load64(Kg + (size_t)(it + 1) * 128 * CC, sK + ((it + 1) & 1) * 16384);
            loadV(it + 1, sV + ((it + 1) & 1) * 16384);
        }
        CP_COMMIT();
        CP_WAIT1();
        __syncthreads();

        const uint32_t k_s = sK + (it & 1) * 16384;
        const uint32_t v_s = sV + (it & 1) * 16384;

        // ---- S = Q @ K^T  (per warp: 16 rows x 128 keys) ----
        float sacc[16][4];
        #pragma unroll
        for (int i = 0; i < 16; i++)
            #pragma unroll
            for (int j = 0; j < 4; j++) sacc[i][j] = 0.f;

        #pragma unroll
        for (int ks = 0; ks < 4; ks++) {
            uint32_t qf[4];
            {
                int row  = wm + (lane & 15);
                int byte = ks * 32 + ((lane >> 4) << 4);
                ldsm4(qf[0], qf[1], qf[2], qf[3], sQ + SW128(row * 128 + byte));
            }
            #pragma unroll
            for (int nb = 0; nb < 8; nb++) {
                uint32_t b0, b1, b2, b3;
                int row  = nb * 16 + ((lane >> 4) << 3) + (lane & 7);
                int byte = ks * 32 + (((lane >> 3) & 1) << 4);
                ldsm4(b0, b1, b2, b3, k_s + SW128(row * 128 + byte));
                mma16816(sacc[2 * nb + 0], qf, b0, b1);
                mma16816(sacc[2 * nb + 1], qf, b2, b3);
            }
        }

        // ---- online softmax (rows r = lane>>2 and r+8) ----
        float rmax0 = -INFINITY, rmax1 = -INFINITY;
        #pragma unroll
        for (int nb = 0; nb < 16; nb++) {
            rmax0 = fmaxf(rmax0, fmaxf(sacc[nb][0], sacc[nb][1]));
            rmax1 = fmaxf(rmax1, fmaxf(sacc[nb][2], sacc[nb][3]));
        }
        rmax0 = fmaxf(rmax0, __shfl_xor_sync(0xffffffffu, rmax0, 1));
        rmax0 = fmaxf(rmax0, __shfl_xor_sync(0xffffffffu, rmax0, 2));
        rmax1 = fmaxf(rmax1, __shfl_xor_sync(0xffffffffu, rmax1, 1));
        rmax1 = fmaxf(rmax1, __shfl_xor_sync(0xffffffffu, rmax1, 2));
        const float mn0 = fmaxf(m0, rmax0), mn1 = fmaxf(m1, rmax1);
        const float corr0 = __expf(m0 - mn0), corr1 = __expf(m1 - mn1);
        m0 = mn0; m1 = mn1;
        float rs0 = 0.f, rs1 = 0.f;
        #pragma unroll
        for (int nb = 0; nb < 16; nb++) {
            sacc[nb][0] = __expf(sacc[nb][0] - mn0);
            sacc[nb][1] = __expf(sacc[nb][1] - mn0);
            sacc[nb][2] = __expf(sacc[nb][2] - mn1);
            sacc[nb][3] = __expf(sacc[nb][3] - mn1);
            rs0 += sacc[nb][0] + sacc[nb][1];
            rs1 += sacc[nb][2] + sacc[nb][3];
        }
        rs0 += __shfl_xor_sync(0xffffffffu, rs0, 1);
        rs0 += __shfl_xor_sync(0xffffffffu, rs0, 2);
        rs1 += __shfl_xor_sync(0xffffffffu, rs1, 1);
        rs1 += __shfl_xor_sync(0xffffffffu, rs1, 2);
        l0 = l0 * corr0 + rs0;
        l1 = l1 * corr1 + rs1;
        #pragma unroll
        for (int nb = 0; nb < 8; nb++) {
            oacc[nb][0] *= corr0; oacc[nb][1] *= corr0;
            oacc[nb][2] *= corr1; oacc[nb][3] *= corr1;
        }

        // ---- O += P @ V  (P from sacc registers, V from smem) ----
        #pragma unroll
        for (int ks = 0; ks < 8; ks++) {
            uint32_t pf[4];
            pf[0] = packh2(sacc[2 * ks + 0][0], sacc[2 * ks + 0][1]);
            pf[1] = packh2(sacc[2 * ks + 0][2], sacc[2 * ks + 0][3]);
            pf[2] = packh2(sacc[2 * ks + 1][0], sacc[2 * ks + 1][1]);
            pf[3] = packh2(sacc[2 * ks + 1][2], sacc[2 * ks + 1][3]);
            const uint32_t vbase = v_s + (ks >> 2) * 8192;
            #pragma unroll
            for (int nb = 0; nb < 4; nb++) {
                uint32_t b0, b1, b2, b3;
                int row  = nb * 16 + ((lane >> 4) << 3) + (lane & 7);
                int byte = (ks & 3) * 32 + (((lane >> 3) & 1) << 4);
                ldsm4(b0, b1, b2, b3, vbase + SW128(row * 128 + byte));
                mma16816(oacc[2 * nb + 0], pf, b0, b1);
                mma16816(oacc[2 * nb + 1], pf, b2, b3);
            }
        }
        __syncthreads();
    }

    // ---- epilogue: y[b][q0+row][h*64+d] = O / l ----
    const float inv0 = 1.0f / l0, inv1 = 1.0f / l1;
    const int r = lane >> 2, cb = (lane & 3) << 1;
    __half* y0 = yh + (size_t)bz * NN * CC + (size_t)(q0 + wm + r) * CC + hz * DD;
    __half* y1 = y0 + 8 * CC;
    #pragma unroll
    for (int nb = 0; nb < 8; nb++) {
        *(__half2*)&y0[nb * 8 + cb] = __floats2half2_rn(oacc[nb][0] * inv0, oacc[nb][1] * inv0);
        *(__half2*)&y1[nb * 8 + cb] = __floats2half2_rn(oacc[nb][2] * inv1, oacc[nb][3] * inv1);
    }
}

// ---------------- transposes ----------------
__global__ void __launch_bounds__(256) transpose_f2h(
    const float* __restrict__ in, __half* __restrict__ out, int ldi, int ldo)
{
    __shared__ float t[32][33];
    const int r0 = blockIdx.y * 32, c0 = blockIdx.x * 32;
    const int tx = threadIdx.x & 31, ty = threadIdx.x >> 5;
    #pragma unroll
    for (int i = ty; i < 32; i += 8)
        t[i][tx] = in[(size_t)(r0 + i) * ldi + c0 + tx];
    __syncthreads();
    #pragma unroll
    for (int i = ty; i < 32; i += 8)
        out[(size_t)(c0 + i) * ldo + r0 + tx] = __float2half(t[tx][i]);
}

__global__ void __launch_bounds__(256) transpose_h2h(
    const __half* __restrict__ in, __half* __restrict__ out,
    int ldi, int ldo, long bsi, long hsi, long bso, long hso, int H)
{
    __shared__ __half t[32][34];
    const int z = blockIdx.z, bz = z / H, hz = z % H;
    in  += (size_t)bz * bsi + (size_t)hz * hsi;
    out += (size_t)bz * bso + (size_t)hz * hso;
    const int r0 = blockIdx.y * 32, c0 = blockIdx.x * 32;
    const int tx = threadIdx.x & 31, ty = threadIdx.x >> 5;
    #pragma unroll
    for (int i = ty; i < 32; i += 8)
        t[i][tx] = in[(size_t)(r0 + i) * ldi + c0 + tx];
    __syncthreads();
    #pragma unroll
    for (int i = ty; i < 32; i += 8)
        out[(size_t)(c0 + i) * ldo + r0 + tx] = t[tx][i];
}

// ---------------- block reductions ----------------
__device__ __forceinline__ float blockReduceSum(float val) {
    __shared__ float sh[33];
    int lane = threadIdx.x & 31, wid = threadIdx.x >> 5;
    #pragma unroll
    for (int o = 16; o; o >>= 1) val += __shfl_xor_sync(0xffffffffu, val, o);
    if (!lane) sh[wid] = val;
    __syncthreads();
    int nw = blockDim.x >> 5;
    if (wid == 0) {
        float v = (lane < nw) ? sh[lane] : 0.f;
        #pragma unroll
        for (int o = 16; o; o >>= 1) v += __shfl_xor_sync(0xffffffffu, v, o);
        if (!lane) sh[32] = v;
    }
    __syncthreads();
    float r = sh[32];
    __syncthreads();
    return r;
}

// ---------------- LayerNorm (fp32 in -> fp16 out) ----------------
__global__ __launch_bounds__(256) void ln_h(const float* __restrict__ x,
                                            const float* __restrict__ gamma,
                                            const float* __restrict__ beta,
                                            __half* __restrict__ out) {
    const size_t roff = (size_t)blockIdx.x * CC;
    const float4 v = ((const float4*)(x + roff))[threadIdx.x];
    float mu = blockReduceSum(v.x + v.y + v.z + v.w) * (1.0f / CC);
    float dx = v.x - mu, dy = v.y - mu, dz = v.z - mu, dw = v.w - mu;
    float var = blockReduceSum(dx*dx + dy*dy + dz*dz + dw*dw) * (1.0f / CC);
    float rstd = rsqrtf(var + 1e-6f);
    float4 g = ((const float4*)gamma)[threadIdx.x];
    float4 b = ((const float4*)beta)[threadIdx.x];
    __half2* o2 = (__half2*)(out + roff);
    o2[2 * threadIdx.x + 0] = __floats2half2_rn(dx*rstd*g.x + b.x, dy*rstd*g.y + b.y);
    o2[2 * threadIdx.x + 1] = __floats2half2_rn(dz*rstd*g.z + b.z, dw*rstd*g.w + b.w);
}

// ---------------- launch ----------------
extern "C" void kernel_launch(void* const* d_in, const int* in_sizes, int n_in,
                              void* d_out, int out_size) {
    const float* x      = (const float*)d_in[0];
    const float* Wq     = (const float*)d_in[1];
    const float* Wk     = (const float*)d_in[2];
    const float* Wv     = (const float*)d_in[3];
    const float* Wp     = (const float*)d_in[4];
    const float* bp     = (const float*)d_in[5];
    const float* W1     = (const float*)d_in[6];
    const float* b1     = (const float*)d_in[7];
    const float* W2     = (const float*)d_in[8];
    const float* b2     = (const float*)d_in[9];
    const float* gamma1 = (const float*)d_in[10];
    const float* beta1  = (const float*)d_in[11];
    const float* gamma2 = (const float*)d_in[12];
    const float* beta2  = (const float*)d_in[13];
    float* out = (float*)d_out;

    __half *xnh,*qh,*kh,*vh,*vth,*yh,*hh,*wqT,*wkT,*wvT,*wpT,*w1T,*w2T;
    float *x1;
    cudaGetSymbolAddress((void**)&xnh, g_xnh); cudaGetSymbolAddress((void**)&qh, g_qh);
    cudaGetSymbolAddress((void**)&kh, g_kh);   cudaGetSymbolAddress((void**)&vh, g_vh);
    cudaGetSymbolAddress((void**)&vth, g_vth); cudaGetSymbolAddress((void**)&yh, g_yh);
    cudaGetSymbolAddress((void**)&x1, g_x1);   cudaGetSymbolAddress((void**)&hh, g_hh);
    cudaGetSymbolAddress((void**)&wqT, g_wqT); cudaGetSymbolAddress((void**)&wkT, g_wkT);
    cudaGetSymbolAddress((void**)&wvT, g_wvT); cudaGetSymbolAddress((void**)&wpT, g_wpT);
    cudaGetSymbolAddress((void**)&w1T, g_w1T); cudaGetSymbolAddress((void**)&w2T, g_w2T);

    const int SM128 = 1024 + 3 * 16384 + 3 * 16384;  // 99328
    const int SMF   = 1024 + 5 * 16384;              // 82944 (flash)
    cudaFuncSetAttribute(hgemm<128,0,true >, cudaFuncAttributeMaxDynamicSharedMemorySize, SM128);
    cudaFuncSetAttribute(hgemm<128,1,false>, cudaFuncAttributeMaxDynamicSharedMemorySize, SM128);
    cudaFuncSetAttribute(hgemm<128,2,true >, cudaFuncAttributeMaxDynamicSharedMemorySize, SM128);
    cudaFuncSetAttribute(flash_attn,         cudaFuncAttributeMaxDynamicSharedMemorySize, SMF);

    dim3 t256(256);

    // 0) weight transposes + fp16 convert
    transpose_f2h<<<dim3(CC/32, CC/32), t256>>>(Wq, wqT, CC, CC);
    transpose_f2h<<<dim3(CC/32, CC/32), t256>>>(Wk, wkT, CC, CC);
    transpose_f2h<<<dim3(CC/32, CC/32), t256>>>(Wv, wvT, CC, CC);
    transpose_f2h<<<dim3(CC/32, CC/32), t256>>>(Wp, wpT, CC, CC);
    transpose_f2h<<<dim3(FF/32, CC/32), t256>>>(W1, w1T, FF, CC);
    transpose_f2h<<<dim3(CC/32, FF/32), t256>>>(W2, w2T, CC, FF);

    // 1) LN1 -> fp16
    ln_h<<<ROWS, 256>>>(x, gamma1, beta1, xnh);

    // 2) QKV projections (q pre-scaled by D^-0.5)
    hgemm<128,0,true><<<dim3(CC/128, ROWS/128, 1), t256, SM128>>>(
        xnh, wqT, qh, nullptr, nullptr, CC, CC, CC, CC, 0,0,0,0,0,0, 1, 0.125f);
    hgemm<128,0,true><<<dim3(CC/128, ROWS/128, 1), t256, SM128>>>(
        xnh, wkT, kh, nullptr, nullptr, CC, CC, CC, CC, 0,0,0,0,0,0, 1, 1.0f);
    hgemm<128,0,true><<<dim3(CC/128, ROWS/128, 1), t256, SM128>>>(
        xnh, wvT, vh, nullptr, nullptr, CC, CC, CC, CC, 0,0,0,0,0,0, 1, 1.0f);

    // 3) per-head V transpose: v[b][n][h*64+d] -> vt[z][d][n]
    transpose_h2h<<<dim3(DD/32, NN/32, BB*HH), t256>>>(
        vh, vth, CC, NN, (long)NN*CC, (long)DD, (long)HH*DD*NN, (long)DD*NN, HH);

    // 4) fused attention: y = softmax(QK^T) V
    flash_attn<<<dim3(NN/128, BB*HH), t256, SMF>>>(qh, kh, vth, yh);

    // 5) x1 = x + y @ Wp + bp   (fp32 out)
    hgemm<128,1,false><<<dim3(CC/128, ROWS/128, 1), t256, SM128>>>(
        yh, wpT, x1, bp, x, CC, CC, CC, CC, 0,0,0,0,0,0, 1, 1.0f);

    // 6) LN2 -> fp16
    ln_h<<<ROWS, 256>>>(x1, gamma2, beta2, xnh);

    // 7) h = gelu(xn @ W1 + b1)
    hgemm<128,2,true><<<dim3(FF/128, ROWS/128, 1), t256, SM128>>>(
        xnh, w1T, hh, b1, nullptr, CC, CC, CC, FF, 0,0,0,0,0,0, 1, 1.0f);

    // 8) out = x1 + h @ W2 + b2  (fp32 out)
    hgemm<128,1,false><<<dim3(CC/128, ROWS/128, 1), t256, SM128>>>(
        hh, w2T, out, b2, x1, FF, FF, FF, CC, 0,0,0,0,0,0, 1, 1.0f);
}